// round 6
// baseline (speedup 1.0000x reference)
#include <cuda_runtime.h>
#include <math.h>

// ---------------------------------------------------------------------------
// Problem constants
// ---------------------------------------------------------------------------
#define S_LEN  2048
#define HID    2560
#define QKV_N  3072          // NH*D + 2*NKV*D
#define NPAIR  20            // NH/2
#define SCALE_F 0.125f       // 1/sqrt(64)

// ---------------------------------------------------------------------------
// Scratch (no allocations allowed -> __device__ globals)
// ---------------------------------------------------------------------------
__device__ float g_qkv [S_LEN * QKV_N];
__device__ float g_attn[S_LEN * HID];
__device__ float g_lambda;

// ---------------------------------------------------------------------------
// helpers
// ---------------------------------------------------------------------------
__device__ __forceinline__ unsigned f2tf32(float x) {
    unsigned r;
    asm("cvt.rna.tf32.f32 %0, %1;" : "=r"(r) : "f"(x));
    return r;
}

__device__ __forceinline__ void mma_tf32(float* c, const unsigned* a, const unsigned* b) {
    asm volatile(
        "mma.sync.aligned.m16n8k8.row.col.f32.tf32.tf32.f32 "
        "{%0,%1,%2,%3}, {%4,%5,%6,%7}, {%8,%9}, {%0,%1,%2,%3};"
        : "+f"(c[0]), "+f"(c[1]), "+f"(c[2]), "+f"(c[3])
        : "r"(a[0]), "r"(a[1]), "r"(a[2]), "r"(a[3]), "r"(b[0]), "r"(b[1]));
}

// ldmatrix x4: threads 0-7 give row addrs of matrix0, 8-15 m1, 16-23 m2, 24-31 m3.
// For tf32 16x8 A-tile: m0=rows0-7/k0-3, m1=rows8-15/k0-3, m2=rows0-7/k4-7, m3=rows8-15/k4-7
// -> r0..r3 == a0..a3.  For two stacked 8-row B-tiles: r0,r1 = b0 of tile0,1; r2,r3 = b1.
__device__ __forceinline__ void ldsm_x4(unsigned* r, const void* p) {
    unsigned a = (unsigned)__cvta_generic_to_shared(p);
    asm volatile("ldmatrix.sync.aligned.m8n8.x4.shared.b16 {%0,%1,%2,%3}, [%4];"
                 : "=r"(r[0]), "=r"(r[1]), "=r"(r[2]), "=r"(r[3]) : "r"(a));
}

// ---------------------------------------------------------------------------
// tf32 GEMM, 2-stage double-buffered, ldmatrix fragments.
// C[M,N] = A[M,K] @ B[N,K]^T + bias[N]
// 128x128 block, GBK=16, 256 threads, 64x32 warp tile.
// Tiles [row][k] stride 20 -> LDSM rows 20i mod 32 distinct: conflict-free.
// ---------------------------------------------------------------------------
#define GBK 16
#define KSTR 20

__global__ __launch_bounds__(256, 2)
void gemm_tf32(const float* __restrict__ A, const float* __restrict__ B,
               const float* __restrict__ bias, float* __restrict__ C,
               int M, int N, int K)
{
    __shared__ unsigned As[2][128 * KSTR];
    __shared__ unsigned Bs[2][128 * KSTR];

    const int tid  = threadIdx.x;
    const int lane = tid & 31;
    const int wid  = tid >> 5;
    const int g    = lane >> 2;
    const int tg   = lane & 3;
    const int i8   = lane & 7;           // ldmatrix row-within-matrix
    const int mr   = (lane >> 3) & 1;    // +8 rows
    const int mc   = (lane >> 4) & 1;    // +4 k-words
    const int warp_m = (wid & 1) * 64;
    const int warp_n = (wid >> 1) * 32;
    const int bm = blockIdx.y * 128;
    const int bn = blockIdx.x * 128;

    const int r0l = tid >> 2;
    const int r1l = (tid + 256) >> 2;
    const int c4l = (tid & 3) << 2;

    float acc[4][4][4];
#pragma unroll
    for (int mt = 0; mt < 4; mt++)
#pragma unroll
        for (int nt = 0; nt < 4; nt++)
#pragma unroll
            for (int r = 0; r < 4; r++) acc[mt][nt][r] = 0.f;

    float4 pa0, pa1, pb0, pb1;

    pa0 = *(const float4*)(A + (size_t)(bm + r0l) * K + c4l);
    pa1 = *(const float4*)(A + (size_t)(bm + r1l) * K + c4l);
    pb0 = *(const float4*)(B + (size_t)(bn + r0l) * K + c4l);
    pb1 = *(const float4*)(B + (size_t)(bn + r1l) * K + c4l);
    {
        uint4 u;
        u.x = f2tf32(pa0.x); u.y = f2tf32(pa0.y); u.z = f2tf32(pa0.z); u.w = f2tf32(pa0.w);
        *(uint4*)(&As[0][r0l * KSTR + c4l]) = u;
        u.x = f2tf32(pa1.x); u.y = f2tf32(pa1.y); u.z = f2tf32(pa1.z); u.w = f2tf32(pa1.w);
        *(uint4*)(&As[0][r1l * KSTR + c4l]) = u;
        u.x = f2tf32(pb0.x); u.y = f2tf32(pb0.y); u.z = f2tf32(pb0.z); u.w = f2tf32(pb0.w);
        *(uint4*)(&Bs[0][r0l * KSTR + c4l]) = u;
        u.x = f2tf32(pb1.x); u.y = f2tf32(pb1.y); u.z = f2tf32(pb1.z); u.w = f2tf32(pb1.w);
        *(uint4*)(&Bs[0][r1l * KSTR + c4l]) = u;
    }
    __syncthreads();

    int buf = 0;
    for (int k0 = 0; k0 < K; k0 += GBK) {
        const bool more = (k0 + GBK) < K;
        if (more) {
            const float* Ak = A + k0 + GBK + c4l;
            const float* Bk = B + k0 + GBK + c4l;
            pa0 = *(const float4*)(Ak + (size_t)(bm + r0l) * K);
            pa1 = *(const float4*)(Ak + (size_t)(bm + r1l) * K);
            pb0 = *(const float4*)(Bk + (size_t)(bn + r0l) * K);
            pb1 = *(const float4*)(Bk + (size_t)(bn + r1l) * K);
        }

#pragma unroll
        for (int kk = 0; kk < GBK; kk += 8) {
            unsigned afr[4][4];
#pragma unroll
            for (int mt = 0; mt < 4; mt++)
                ldsm_x4(afr[mt],
                        &As[buf][(warp_m + 16 * mt + i8 + 8 * mr) * KSTR + kk + 4 * mc]);
            unsigned bq[2][4];
#pragma unroll
            for (int ntp = 0; ntp < 2; ntp++)
                ldsm_x4(bq[ntp],
                        &Bs[buf][(warp_n + 16 * ntp + i8 + 8 * mr) * KSTR + kk + 4 * mc]);
#pragma unroll
            for (int mt = 0; mt < 4; mt++)
#pragma unroll
                for (int nt = 0; nt < 4; nt++) {
                    unsigned bf[2] = { bq[nt >> 1][nt & 1], bq[nt >> 1][2 + (nt & 1)] };
                    mma_tf32(acc[mt][nt], afr[mt], bf);
                }
        }

        if (more) {
            uint4 u;
            u.x = f2tf32(pa0.x); u.y = f2tf32(pa0.y); u.z = f2tf32(pa0.z); u.w = f2tf32(pa0.w);
            *(uint4*)(&As[buf ^ 1][r0l * KSTR + c4l]) = u;
            u.x = f2tf32(pa1.x); u.y = f2tf32(pa1.y); u.z = f2tf32(pa1.z); u.w = f2tf32(pa1.w);
            *(uint4*)(&As[buf ^ 1][r1l * KSTR + c4l]) = u;
            u.x = f2tf32(pb0.x); u.y = f2tf32(pb0.y); u.z = f2tf32(pb0.z); u.w = f2tf32(pb0.w);
            *(uint4*)(&Bs[buf ^ 1][r0l * KSTR + c4l]) = u;
            u.x = f2tf32(pb1.x); u.y = f2tf32(pb1.y); u.z = f2tf32(pb1.z); u.w = f2tf32(pb1.w);
            *(uint4*)(&Bs[buf ^ 1][r1l * KSTR + c4l]) = u;
        }
        __syncthreads();
        buf ^= 1;
    }

#pragma unroll
    for (int mt = 0; mt < 4; mt++) {
#pragma unroll
        for (int nt = 0; nt < 4; nt++) {
            int row0 = bm + warp_m + 16 * mt + g;
            int col0 = bn + warp_n + 8 * nt + 2 * tg;
            float bx = bias[col0], by = bias[col0 + 1];
            float2 lo = { acc[mt][nt][0] + bx, acc[mt][nt][1] + by };
            float2 hi = { acc[mt][nt][2] + bx, acc[mt][nt][3] + by };
            *(float2*)(C + (size_t)row0 * N + col0)       = lo;
            *(float2*)(C + (size_t)(row0 + 8) * N + col0) = hi;
        }
    }
}

// ---------------------------------------------------------------------------
// Fused differential flash attention, tf32 + ldmatrix.
// Block = 64 queries x pair-head, both paths (warps 0-3 path0, 4-7 path1).
// V stored TRANSPOSED [n][k] so PV B-fragments come via LDSM.x4.
// smem words: QP 2x64x68 | K 2x64x68 (reused as xchg) | VT 128x68.
// ---------------------------------------------------------------------------
#define AQ 68
#define AVT 68
#define XST 132
#define ATT_SMEM ((4 * 64 * AQ + 128 * AVT) * 4)   // 104448 bytes

__global__ __launch_bounds__(256)
void attn_fused(const float* __restrict__ qkv, const float* __restrict__ subln,
                float* __restrict__ Aout)
{
    extern __shared__ unsigned su[];
    unsigned* uQP = su;                    // per path: 64*AQ ; Q then P
    unsigned* uK  = su + 2 * 64 * AQ;      // per path: 64*AQ ; later exchange
    unsigned* uVT = su + 4 * 64 * AQ;      // 128*AVT  (V transposed [n][k])
    float* xbuf = (float*)uK;

    const int tid  = threadIdx.x;
    const int lane = tid & 31;
    const int wid  = tid >> 5;
    const int g    = lane >> 2;
    const int tg   = lane & 3;
    const int i8   = lane & 7;
    const int mr   = (lane >> 3) & 1;
    const int mc   = (lane >> 4) & 1;
    const int pth  = wid >> 2;
    const int i0w  = (wid & 3) * 16;
    const int tid2 = tid & 127;

    const int i0 = blockIdx.x * 64;
    const int p  = blockIdx.y;
    const int gp = p / 10;
    const int qoff = (2 * p + pth) * 64;
    const int koff = 2560 + (2 * gp + pth) * 64;
    const int voff = 2816 + 2 * gp * 64;

    unsigned* uQp = uQP + pth * (64 * AQ);
    unsigned* uKp = uK  + pth * (64 * AQ);

    // ---- Load this path's Q tile (64x64), scale, tf32 ----
#pragma unroll
    for (int it = 0; it < 8; it++) {
        int lin = it * 128 + tid2;
        int row = lin >> 4;
        int c4  = (lin & 15) << 2;
        float4 v = *(const float4*)(qkv + (size_t)(i0 + row) * QKV_N + qoff + c4);
        uint4 u = { f2tf32(v.x * SCALE_F), f2tf32(v.y * SCALE_F),
                    f2tf32(v.z * SCALE_F), f2tf32(v.w * SCALE_F) };
        *(uint4*)(uQp + row * AQ + c4) = u;
    }
    __syncthreads();

    // ---- Preload Q fragments (Q smem dead afterwards; region reused for P) ----
    unsigned qf[8][4];
#pragma unroll
    for (int k = 0; k < 8; k++)
        ldsm_x4(qf[k], uQp + (i0w + i8 + 8 * mr) * AQ + k * 8 + 4 * mc);

    float m0 = -1e30f, m1 = -1e30f, l0 = 0.f, l1 = 0.f;
    float oacc[16][4];
#pragma unroll
    for (int nt = 0; nt < 16; nt++)
#pragma unroll
        for (int r = 0; r < 4; r++) oacc[nt][r] = 0.f;

    for (int j0 = 0; j0 <= i0; j0 += 64) {
        __syncthreads();

        // ---- this path's K tile (64x64) [n][k] ----
#pragma unroll
        for (int it = 0; it < 8; it++) {
            int lin = it * 128 + tid2;
            int row = lin >> 4;
            int c4  = (lin & 15) << 2;
            float4 v = *(const float4*)(qkv + (size_t)(j0 + row) * QKV_N + koff + c4);
            uint4 u = { f2tf32(v.x), f2tf32(v.y), f2tf32(v.z), f2tf32(v.w) };
            *(uint4*)(uKp + row * AQ + c4) = u;
        }
        // ---- shared V tile, stored TRANSPOSED [n=0..127][k=0..63] ----
        // lane-per-k-row mapping -> stride-1 STS (conflict-free)
#pragma unroll
        for (int it = 0; it < 8; it++) {
            int row = 32 * (it & 1) + lane;              // k
            int n0  = ((tid >> 5) + 8 * (it >> 1)) << 2; // n base (0,4,..,124)
            float4 v = *(const float4*)(qkv + (size_t)(j0 + row) * QKV_N + voff + n0);
            uVT[(n0 + 0) * AVT + row] = f2tf32(v.x);
            uVT[(n0 + 1) * AVT + row] = f2tf32(v.y);
            uVT[(n0 + 2) * AVT + row] = f2tf32(v.z);
            uVT[(n0 + 3) * AVT + row] = f2tf32(v.w);
        }
        __syncthreads();

        // ---- S = Q K^T ----
        float sacc[8][4];
#pragma unroll
        for (int nt = 0; nt < 8; nt++)
#pragma unroll
            for (int r = 0; r < 4; r++) sacc[nt][r] = 0.f;

#pragma unroll
        for (int k = 0; k < 8; k++) {
            int kk8 = k * 8;
            unsigned kq[4][4];
#pragma unroll
            for (int ntp = 0; ntp < 4; ntp++)
                ldsm_x4(kq[ntp], uKp + (16 * ntp + i8 + 8 * mr) * AQ + kk8 + 4 * mc);
#pragma unroll
            for (int nt = 0; nt < 8; nt++) {
                unsigned bf[2] = { kq[nt >> 1][nt & 1], kq[nt >> 1][2 + (nt & 1)] };
                mma_tf32(sacc[nt], qf[k], bf);
            }
        }

        // ---- causal mask on diagonal block ----
        if (j0 == i0) {
            int r0 = i0w + g, r1 = r0 + 8;
#pragma unroll
            for (int nt = 0; nt < 8; nt++) {
                int c0 = nt * 8 + 2 * tg;
                if (c0     > r0) sacc[nt][0] = -1e30f;
                if (c0 + 1 > r0) sacc[nt][1] = -1e30f;
                if (c0     > r1) sacc[nt][2] = -1e30f;
                if (c0 + 1 > r1) sacc[nt][3] = -1e30f;
            }
        }

        // ---- online softmax ----
        float tm0 = -1e30f, tm1 = -1e30f;
#pragma unroll
        for (int nt = 0; nt < 8; nt++) {
            tm0 = fmaxf(tm0, fmaxf(sacc[nt][0], sacc[nt][1]));
            tm1 = fmaxf(tm1, fmaxf(sacc[nt][2], sacc[nt][3]));
        }
        tm0 = fmaxf(tm0, __shfl_xor_sync(0xffffffffu, tm0, 1));
        tm0 = fmaxf(tm0, __shfl_xor_sync(0xffffffffu, tm0, 2));
        tm1 = fmaxf(tm1, __shfl_xor_sync(0xffffffffu, tm1, 1));
        tm1 = fmaxf(tm1, __shfl_xor_sync(0xffffffffu, tm1, 2));

        float mn0 = fmaxf(m0, tm0), sc0 = __expf(m0 - mn0);
        float mn1 = fmaxf(m1, tm1), sc1 = __expf(m1 - mn1);

        float rs0 = 0.f, rs1 = 0.f;
#pragma unroll
        for (int nt = 0; nt < 8; nt++) {
            unsigned u0 = f2tf32(__expf(sacc[nt][0] - mn0));
            unsigned u1 = f2tf32(__expf(sacc[nt][1] - mn0));
            unsigned u2 = f2tf32(__expf(sacc[nt][2] - mn1));
            unsigned u3 = f2tf32(__expf(sacc[nt][3] - mn1));
            rs0 += __uint_as_float(u0) + __uint_as_float(u1);
            rs1 += __uint_as_float(u2) + __uint_as_float(u3);
            uint2 lo = { u0, u1 }, hi = { u2, u3 };
            *(uint2*)(uQp + (i0w + g)     * AQ + nt * 8 + 2 * tg) = lo;
            *(uint2*)(uQp + (i0w + g + 8) * AQ + nt * 8 + 2 * tg) = hi;
        }
        rs0 += __shfl_xor_sync(0xffffffffu, rs0, 1);
        rs0 += __shfl_xor_sync(0xffffffffu, rs0, 2);
        rs1 += __shfl_xor_sync(0xffffffffu, rs1, 1);
        rs1 += __shfl_xor_sync(0xffffffffu, rs1, 2);

        l0 = l0 * sc0 + rs0;  m0 = mn0;
        l1 = l1 * sc1 + rs1;  m1 = mn1;
#pragma unroll
        for (int nt = 0; nt < 16; nt++) {
            oacc[nt][0] *= sc0; oacc[nt][1] *= sc0;
            oacc[nt][2] *= sc1; oacc[nt][3] *= sc1;
        }
        __syncwarp();   // P rows are per-warp private

        // ---- O += P V  (P via LDSM, V^T via LDSM) ----
#pragma unroll
        for (int k = 0; k < 8; k++) {
            int kk8 = k * 8;
            unsigned pf[4];
            ldsm_x4(pf, uQp + (i0w + i8 + 8 * mr) * AQ + kk8 + 4 * mc);
#pragma unroll
            for (int ntp = 0; ntp < 8; ntp++) {
                unsigned vq[4];
                ldsm_x4(vq, uVT + (16 * ntp + i8 + 8 * mr) * AVT + kk8 + 4 * mc);
                unsigned bf0[2] = { vq[0], vq[2] };
                unsigned bf1[2] = { vq[1], vq[3] };
                mma_tf32(oacc[2 * ntp],     pf, bf0);
                mma_tf32(oacc[2 * ntp + 1], pf, bf1);
            }
        }
    }

    // ---- combine: path1 exports normalized O2; path0 does diff + RMSNorm ----
    const float inv0 = 1.f / l0, inv1 = 1.f / l1;
    __syncthreads();

    if (pth == 1) {
#pragma unroll
        for (int nt = 0; nt < 16; nt++) {
            int col = nt * 8 + 2 * tg;
            float2 lo = { oacc[nt][0] * inv0, oacc[nt][1] * inv0 };
            float2 hi = { oacc[nt][2] * inv1, oacc[nt][3] * inv1 };
            *(float2*)(xbuf + (i0w + g)     * XST + col) = lo;
            *(float2*)(xbuf + (i0w + g + 8) * XST + col) = hi;
        }
    }
    __syncthreads();

    if (pth == 0) {
        const float lam = g_lambda;
        const float li  = 0.8f - 0.6f * expf(-0.3f * 17.0f);
        float ss0 = 0.f, ss1 = 0.f;
#pragma unroll
        for (int nt = 0; nt < 16; nt++) {
            int col = nt * 8 + 2 * tg;
            float2 o2a = *(float2*)(xbuf + (i0w + g)     * XST + col);
            float2 o2b = *(float2*)(xbuf + (i0w + g + 8) * XST + col);
            float v0 = oacc[nt][0] * inv0 - lam * o2a.x;
            float v1 = oacc[nt][1] * inv0 - lam * o2a.y;
            float v2 = oacc[nt][2] * inv1 - lam * o2b.x;
            float v3 = oacc[nt][3] * inv1 - lam * o2b.y;
            oacc[nt][0] = v0; oacc[nt][1] = v1; oacc[nt][2] = v2; oacc[nt][3] = v3;
            ss0 += v0 * v0 + v1 * v1;
            ss1 += v2 * v2 + v3 * v3;
        }
        ss0 += __shfl_xor_sync(0xffffffffu, ss0, 1);
        ss0 += __shfl_xor_sync(0xffffffffu, ss0, 2);
        ss1 += __shfl_xor_sync(0xffffffffu, ss1, 1);
        ss1 += __shfl_xor_sync(0xffffffffu, ss1, 2);

        const float rms0 = rsqrtf(ss0 * (1.f / 128.f) + 1e-5f) * (1.f - li);
        const float rms1 = rsqrtf(ss1 * (1.f / 128.f) + 1e-5f) * (1.f - li);
        const int row0 = i0 + i0w + g;
#pragma unroll
        for (int nt = 0; nt < 16; nt++) {
            int col = nt * 8 + 2 * tg;
            float w0 = subln[col], w1 = subln[col + 1];
            float2 lo = { oacc[nt][0] * rms0 * w0, oacc[nt][1] * rms0 * w1 };
            float2 hi = { oacc[nt][2] * rms1 * w0, oacc[nt][3] * rms1 * w1 };
            *(float2*)(Aout + (size_t)row0 * HID + p * 128 + col)       = lo;
            *(float2*)(Aout + (size_t)(row0 + 8) * HID + p * 128 + col) = hi;
        }
    }
}

// ---------------------------------------------------------------------------
// lambda_full
// ---------------------------------------------------------------------------
__global__ void lambda_kernel(const float* __restrict__ lq1, const float* __restrict__ lk1,
                              const float* __restrict__ lq2, const float* __restrict__ lk2)
{
    __shared__ float sa[64], sb[64];
    int t = threadIdx.x;
    sa[t] = lq1[t] * lk1[t];
    sb[t] = lq2[t] * lk2[t];
    __syncthreads();
    if (t == 0) {
        float s1 = 0.f, s2 = 0.f;
        for (int i = 0; i < 64; i++) { s1 += sa[i]; s2 += sb[i]; }
        const float lambda_init = 0.8f - 0.6f * expf(-0.3f * 17.0f);
        g_lambda = expf(s1) - expf(s2) + lambda_init;
    }
}

// ---------------------------------------------------------------------------
// Launch
// ---------------------------------------------------------------------------
extern "C" void kernel_launch(void* const* d_in, const int* in_sizes, int n_in,
                              void* d_out, int out_size)
{
    const float* hidden = (const float*)d_in[0];
    const float* Wqkv_w = (const float*)d_in[1];
    const float* Wqkv_b = (const float*)d_in[2];
    const float* out_w  = (const float*)d_in[3];
    const float* out_b  = (const float*)d_in[4];
    const float* lq1    = (const float*)d_in[5];
    const float* lk1    = (const float*)d_in[6];
    const float* lq2    = (const float*)d_in[7];
    const float* lk2    = (const float*)d_in[8];
    const float* subln  = (const float*)d_in[9];
    float* out = (float*)d_out;

    float *qkv, *attn;
    cudaGetSymbolAddress((void**)&qkv,  g_qkv);
    cudaGetSymbolAddress((void**)&attn, g_attn);

    cudaFuncSetAttribute(attn_fused,
                         cudaFuncAttributeMaxDynamicSharedMemorySize, ATT_SMEM);

    // 1) QKV projection
    {
        dim3 grid(QKV_N / 128, S_LEN / 128);
        gemm_tf32<<<grid, 256>>>(hidden, Wqkv_w, Wqkv_b, qkv, S_LEN, QKV_N, HID);
    }

    // 2) lambda scalar
    lambda_kernel<<<1, 64>>>(lq1, lk1, lq2, lk2);

    // 3) Fused differential attention + combine + RMSNorm
    {
        dim3 grid(S_LEN / 64, NPAIR);
        attn_fused<<<grid, 256, ATT_SMEM>>>(qkv, subln, attn);
    }

    // 4) Output projection
    {
        dim3 grid(HID / 128, S_LEN / 128);
        gemm_tf32<<<grid, 256>>>(attn, out_w, out_b, out, S_LEN, HID, HID);
    }
}